// round 1
// baseline (speedup 1.0000x reference)
#include <cuda_runtime.h>
#include <cuda_bf16.h>
#include <math.h>

// ---------------------------------------------------------------------------
// Problem constants: B=2, S=2048, D=1024, H=16, hd=64, FF=4096
// ---------------------------------------------------------------------------
#define M_ROWS 4096          // B*S
#define DMODEL 1024
#define D3     3072
#define DFF    4096
#define NHEADS 16
#define HDIM   64
#define SEQ    2048
#define LN_EPS 1e-5f

// ---------------------------------------------------------------------------
// Scratch (device globals — no runtime allocation allowed)
// ---------------------------------------------------------------------------
__device__ float g_h   [(size_t)M_ROWS * DMODEL];   // LN output (reused for LN2)
__device__ float g_qkv [(size_t)M_ROWS * D3];       // qkv projection
__device__ float g_attn[(size_t)M_ROWS * DMODEL];   // attention output (pre out-proj)
__device__ float g_ff  [(size_t)M_ROWS * DFF];      // gelu(fc1) output

// ---------------------------------------------------------------------------
// LayerNorm: one block per row, 256 threads * 4 floats
// ---------------------------------------------------------------------------
__global__ void ln_kernel(const float* __restrict__ x,
                          const float* __restrict__ gamma,
                          const float* __restrict__ beta,
                          float* __restrict__ y)
{
    const int row = blockIdx.x;
    const int t = threadIdx.x;
    const float4* xr = (const float4*)(x + (size_t)row * DMODEL);
    float4 xv = xr[t];

    __shared__ float red[8];
    __shared__ float stats[2];

    float s = xv.x + xv.y + xv.z + xv.w;
    #pragma unroll
    for (int o = 16; o > 0; o >>= 1) s += __shfl_xor_sync(0xffffffffu, s, o);
    if ((t & 31) == 0) red[t >> 5] = s;
    __syncthreads();
    if (t == 0) {
        float tot = 0.f;
        #pragma unroll
        for (int i = 0; i < 8; i++) tot += red[i];
        stats[0] = tot * (1.0f / DMODEL);
    }
    __syncthreads();
    const float mean = stats[0];

    float dx = xv.x - mean, dy = xv.y - mean, dz = xv.z - mean, dw = xv.w - mean;
    float s2 = dx*dx + dy*dy + dz*dz + dw*dw;
    #pragma unroll
    for (int o = 16; o > 0; o >>= 1) s2 += __shfl_xor_sync(0xffffffffu, s2, o);
    if ((t & 31) == 0) red[t >> 5] = s2;
    __syncthreads();
    if (t == 0) {
        float tot = 0.f;
        #pragma unroll
        for (int i = 0; i < 8; i++) tot += red[i];
        stats[1] = rsqrtf(tot * (1.0f / DMODEL) + LN_EPS);
    }
    __syncthreads();
    const float rstd = stats[1];

    float4 g4 = ((const float4*)gamma)[t];
    float4 b4 = ((const float4*)beta)[t];
    float4 o;
    o.x = dx * rstd * g4.x + b4.x;
    o.y = dy * rstd * g4.y + b4.y;
    o.z = dz * rstd * g4.z + b4.z;
    o.w = dw * rstd * g4.w + b4.w;
    ((float4*)(y + (size_t)row * DMODEL))[t] = o;
}

// ---------------------------------------------------------------------------
// NT SGEMM: C[M,N] = A[M,K] * W[N,K]^T + bias, with optional epilogue.
// BM=BN=128, BK=16, 256 threads, 8x8 per thread.
// EPI: 0 = bias, 1 = bias+exact GELU, 2 = bias + residual add
// ---------------------------------------------------------------------------
#define BM 128
#define BN 128
#define BK 16
#define SMP (BM + 4)   // padded row length (132 floats; keeps float4 alignment)

__device__ __forceinline__ float gelu_exact(float v) {
    return 0.5f * v * (1.0f + erff(v * 0.70710678118654752f));
}

template<int EPI>
__global__ __launch_bounds__(256, 2)
void gemm_nt(const float* __restrict__ A, const float* __restrict__ W,
             const float* __restrict__ bias, const float* __restrict__ res,
             float* __restrict__ C, int M, int N, int K)
{
    __shared__ float As[BK][SMP];
    __shared__ float Ws[BK][SMP];

    const int tid = threadIdx.x;
    const int bm = blockIdx.y * BM;
    const int bn = blockIdx.x * BN;
    const int tx = tid & 15;
    const int ty = tid >> 4;

    const int lrow  = tid >> 2;      // 0..63
    const int lcol4 = tid & 3;       // 0..3 (float4 within 16-wide K slab)

    float acc[8][8];
    #pragma unroll
    for (int i = 0; i < 8; i++)
        #pragma unroll
        for (int j = 0; j < 8; j++) acc[i][j] = 0.f;

    for (int k0 = 0; k0 < K; k0 += BK) {
        #pragma unroll
        for (int p = 0; p < 2; p++) {
            const int r = lrow + p * 64;
            float4 a = *(const float4*)(A + (size_t)(bm + r) * K + k0 + lcol4 * 4);
            As[lcol4*4 + 0][r] = a.x;
            As[lcol4*4 + 1][r] = a.y;
            As[lcol4*4 + 2][r] = a.z;
            As[lcol4*4 + 3][r] = a.w;
            float4 w = *(const float4*)(W + (size_t)(bn + r) * K + k0 + lcol4 * 4);
            Ws[lcol4*4 + 0][r] = w.x;
            Ws[lcol4*4 + 1][r] = w.y;
            Ws[lcol4*4 + 2][r] = w.z;
            Ws[lcol4*4 + 3][r] = w.w;
        }
        __syncthreads();

        #pragma unroll
        for (int k = 0; k < BK; k++) {
            float4 a0 = *(const float4*)&As[k][ty * 8];
            float4 a1 = *(const float4*)&As[k][ty * 8 + 4];
            float4 w0 = *(const float4*)&Ws[k][tx * 8];
            float4 w1 = *(const float4*)&Ws[k][tx * 8 + 4];
            float av[8] = {a0.x, a0.y, a0.z, a0.w, a1.x, a1.y, a1.z, a1.w};
            float wv[8] = {w0.x, w0.y, w0.z, w0.w, w1.x, w1.y, w1.z, w1.w};
            #pragma unroll
            for (int i = 0; i < 8; i++)
                #pragma unroll
                for (int j = 0; j < 8; j++)
                    acc[i][j] = fmaf(av[i], wv[j], acc[i][j]);
        }
        __syncthreads();
    }

    // epilogue
    #pragma unroll
    for (int i = 0; i < 8; i++) {
        const size_t row = (size_t)(bm + ty * 8 + i);
        float* crow = C + row * N + bn + tx * 8;
        const float* rrow = (EPI == 2) ? (res + row * N + bn + tx * 8) : nullptr;
        #pragma unroll
        for (int j = 0; j < 8; j++) {
            float v = acc[i][j] + bias[bn + tx * 8 + j];
            if (EPI == 1) v = gelu_exact(v);
            if (EPI == 2) v += rrow[j];
            crow[j] = v;
        }
    }
}

// ---------------------------------------------------------------------------
// Flash attention (causal). One block per (q-tile, head, batch).
// BMq = BNk = 64, hd = 64, 256 threads (16x16 of 4x4 micro-tiles).
// Scores kept TRANSPOSED in SMEM: St[k][q] (stride 65) so both GEMM phases
// read the vectorized operand conflict-free, and the per-q softmax reduce
// (thread t owns column q=t) is bank-conflict-free.
// ---------------------------------------------------------------------------
#define ATT_SMEM_FLOATS (64*64*3 + 64*65 + 128)
#define ATT_SMEM_BYTES  (ATT_SMEM_FLOATS * 4)

__global__ __launch_bounds__(256)
void attn_kernel(const float* __restrict__ qkv, float* __restrict__ out)
{
    extern __shared__ float sm[];
    float* Qt = sm;                 // [d][q]   64x64 (d-major), pre-scaled
    float* Ks = sm + 4096;          // [k][d]   64x64
    float* Vs = sm + 8192;          // [k][d]   64x64
    float* St = sm + 12288;         // [k][q]   64x65 (padded)
    float* scale_s = sm + 12288 + 64 * 65;
    float* l_s     = scale_s + 64;

    const int qt = blockIdx.x;      // 0..31
    const int h  = blockIdx.y;      // 0..15
    const int b  = blockIdx.z;      // 0..1
    const int tid = threadIdx.x;
    const int tx = tid & 15, ty = tid >> 4;

    const size_t rs = D3;
    const float* qbase = qkv + (size_t)b * SEQ * rs + h * HDIM;
    const float* kbase = qbase + DMODEL;
    const float* vbase = qbase + 2 * DMODEL;

    // Load Q tile transposed + scaled (1/sqrt(64))
    {
        const int r = tid >> 4, c4 = tid & 15;
        #pragma unroll
        for (int p = 0; p < 4; p++) {
            const int row = r + p * 16;
            float4 q4 = *(const float4*)(qbase + (size_t)(qt * 64 + row) * rs + c4 * 4);
            const float s = 0.125f;
            Qt[(c4*4 + 0) * 64 + row] = q4.x * s;
            Qt[(c4*4 + 1) * 64 + row] = q4.y * s;
            Qt[(c4*4 + 2) * 64 + row] = q4.z * s;
            Qt[(c4*4 + 3) * 64 + row] = q4.w * s;
        }
    }

    float m_i = -1e30f, l_i = 0.f;        // valid in threads 0..63 (col q = tid)
    float acc[4][4];
    #pragma unroll
    for (int i = 0; i < 4; i++)
        #pragma unroll
        for (int j = 0; j < 4; j++) acc[i][j] = 0.f;

    __syncthreads();

    for (int kt = 0; kt <= qt; kt++) {
        // Load K, V tiles (natural [k][d] layout)
        {
            const int r = tid >> 4, c4 = tid & 15;
            #pragma unroll
            for (int p = 0; p < 4; p++) {
                const int row = r + p * 16;
                const size_t g = (size_t)(kt * 64 + row) * rs + c4 * 4;
                *(float4*)(Ks + row * 64 + c4 * 4) = *(const float4*)(kbase + g);
                *(float4*)(Vs + row * 64 + c4 * 4) = *(const float4*)(vbase + g);
            }
        }
        __syncthreads();

        // St[k][q] = sum_d Ks[k][d] * Qt[d][q]
        float sacc[4][4];
        #pragma unroll
        for (int i = 0; i < 4; i++)
            #pragma unroll
            for (int j = 0; j < 4; j++) sacc[i][j] = 0.f;

        #pragma unroll 16
        for (int d = 0; d < 64; d++) {
            float a0 = Ks[(ty*4 + 0) * 64 + d];
            float a1 = Ks[(ty*4 + 1) * 64 + d];
            float a2 = Ks[(ty*4 + 2) * 64 + d];
            float a3 = Ks[(ty*4 + 3) * 64 + d];
            float4 qv = *(const float4*)&Qt[d * 64 + tx * 4];
            sacc[0][0] = fmaf(a0, qv.x, sacc[0][0]); sacc[0][1] = fmaf(a0, qv.y, sacc[0][1]);
            sacc[0][2] = fmaf(a0, qv.z, sacc[0][2]); sacc[0][3] = fmaf(a0, qv.w, sacc[0][3]);
            sacc[1][0] = fmaf(a1, qv.x, sacc[1][0]); sacc[1][1] = fmaf(a1, qv.y, sacc[1][1]);
            sacc[1][2] = fmaf(a1, qv.z, sacc[1][2]); sacc[1][3] = fmaf(a1, qv.w, sacc[1][3]);
            sacc[2][0] = fmaf(a2, qv.x, sacc[2][0]); sacc[2][1] = fmaf(a2, qv.y, sacc[2][1]);
            sacc[2][2] = fmaf(a2, qv.z, sacc[2][2]); sacc[2][3] = fmaf(a2, qv.w, sacc[2][3]);
            sacc[3][0] = fmaf(a3, qv.x, sacc[3][0]); sacc[3][1] = fmaf(a3, qv.y, sacc[3][1]);
            sacc[3][2] = fmaf(a3, qv.z, sacc[3][2]); sacc[3][3] = fmaf(a3, qv.w, sacc[3][3]);
        }

        // Write scores (causal mask on diagonal tile): St[k][q]
        const bool diag = (kt == qt);
        #pragma unroll
        for (int i = 0; i < 4; i++) {
            const int krow = ty * 4 + i;
            #pragma unroll
            for (int j = 0; j < 4; j++) {
                const int qcol = tx * 4 + j;
                float v = sacc[i][j];
                if (diag && krow > qcol) v = -1e30f;
                St[krow * 65 + qcol] = v;
            }
        }
        __syncthreads();

        // Online softmax: thread t (<64) owns q column t
        if (tid < 64) {
            float mx = m_i;
            #pragma unroll 8
            for (int k = 0; k < 64; k++) mx = fmaxf(mx, St[k * 65 + tid]);
            const float fac = __expf(m_i - mx);   // 0 on first tile
            float lsum = 0.f;
            #pragma unroll 8
            for (int k = 0; k < 64; k++) {
                float p = __expf(St[k * 65 + tid] - mx);
                St[k * 65 + tid] = p;
                lsum += p;
            }
            m_i = mx;
            l_i = l_i * fac + lsum;
            scale_s[tid] = fac;
        }
        __syncthreads();

        // O rescale + O += P^T V   (P stored transposed: St[k][q])
        float sc[4];
        #pragma unroll
        for (int i = 0; i < 4; i++) sc[i] = scale_s[ty * 4 + i];
        #pragma unroll
        for (int i = 0; i < 4; i++)
            #pragma unroll
            for (int j = 0; j < 4; j++) acc[i][j] *= sc[i];

        #pragma unroll 8
        for (int kk = 0; kk < 64; kk++) {
            float p0 = St[kk * 65 + ty*4 + 0];
            float p1 = St[kk * 65 + ty*4 + 1];
            float p2 = St[kk * 65 + ty*4 + 2];
            float p3 = St[kk * 65 + ty*4 + 3];
            float4 vv = *(const float4*)&Vs[kk * 64 + tx * 4];
            acc[0][0] = fmaf(p0, vv.x, acc[0][0]); acc[0][1] = fmaf(p0, vv.y, acc[0][1]);
            acc[0][2] = fmaf(p0, vv.z, acc[0][2]); acc[0][3] = fmaf(p0, vv.w, acc[0][3]);
            acc[1][0] = fmaf(p1, vv.x, acc[1][0]); acc[1][1] = fmaf(p1, vv.y, acc[1][1]);
            acc[1][2] = fmaf(p1, vv.z, acc[1][2]); acc[1][3] = fmaf(p1, vv.w, acc[1][3]);
            acc[2][0] = fmaf(p2, vv.x, acc[2][0]); acc[2][1] = fmaf(p2, vv.y, acc[2][1]);
            acc[2][2] = fmaf(p2, vv.z, acc[2][2]); acc[2][3] = fmaf(p2, vv.w, acc[2][3]);
            acc[3][0] = fmaf(p3, vv.x, acc[3][0]); acc[3][1] = fmaf(p3, vv.y, acc[3][1]);
            acc[3][2] = fmaf(p3, vv.z, acc[3][2]); acc[3][3] = fmaf(p3, vv.w, acc[3][3]);
        }
        __syncthreads();   // protect Ks/Vs/St before next iteration
    }

    if (tid < 64) l_s[tid] = l_i;
    __syncthreads();

    #pragma unroll
    for (int i = 0; i < 4; i++) {
        const int q = ty * 4 + i;
        const float inv = 1.0f / l_s[q];
        float4 o;
        o.x = acc[i][0] * inv;
        o.y = acc[i][1] * inv;
        o.z = acc[i][2] * inv;
        o.w = acc[i][3] * inv;
        *(float4*)(out + (size_t)(b * SEQ + qt * 64 + q) * DMODEL + h * HDIM + tx * 4) = o;
    }
}

// ---------------------------------------------------------------------------
// Launch
// ---------------------------------------------------------------------------
extern "C" void kernel_launch(void* const* d_in, const int* in_sizes, int n_in,
                              void* d_out, int out_size)
{
    const float* x     = (const float*)d_in[0];
    const float* ln1_g = (const float*)d_in[1];
    const float* ln1_b = (const float*)d_in[2];
    const float* qkv_w = (const float*)d_in[3];
    const float* qkv_b = (const float*)d_in[4];
    const float* out_w = (const float*)d_in[5];
    const float* out_b = (const float*)d_in[6];
    const float* ln2_g = (const float*)d_in[7];
    const float* ln2_b = (const float*)d_in[8];
    const float* fc1_w = (const float*)d_in[9];
    const float* fc1_b = (const float*)d_in[10];
    const float* fc2_w = (const float*)d_in[11];
    const float* fc2_b = (const float*)d_in[12];
    float* out = (float*)d_out;

    float *h, *qkv, *attn, *ff;
    cudaGetSymbolAddress((void**)&h,    g_h);
    cudaGetSymbolAddress((void**)&qkv,  g_qkv);
    cudaGetSymbolAddress((void**)&attn, g_attn);
    cudaGetSymbolAddress((void**)&ff,   g_ff);

    cudaFuncSetAttribute(attn_kernel,
                         cudaFuncAttributeMaxDynamicSharedMemorySize,
                         ATT_SMEM_BYTES);

    // 1) h = LN1(x)
    ln_kernel<<<M_ROWS, 256>>>(x, ln1_g, ln1_b, h);

    // 2) qkv = h @ qkv_w^T + qkv_b
    gemm_nt<0><<<dim3(D3 / BN, M_ROWS / BM), 256>>>(h, qkv_w, qkv_b, nullptr,
                                                    qkv, M_ROWS, D3, DMODEL);

    // 3) attn = causal_flash_attention(qkv)
    attn_kernel<<<dim3(SEQ / 64, NHEADS, 2), 256, ATT_SMEM_BYTES>>>(qkv, attn);

    // 4) out (x1) = attn @ out_w^T + out_b + x
    gemm_nt<2><<<dim3(DMODEL / BN, M_ROWS / BM), 256>>>(attn, out_w, out_b, x,
                                                        out, M_ROWS, DMODEL, DMODEL);

    // 5) h = LN2(x1)
    ln_kernel<<<M_ROWS, 256>>>(out, ln2_g, ln2_b, h);

    // 6) ff = gelu(h @ fc1_w^T + fc1_b)
    gemm_nt<1><<<dim3(DFF / BN, M_ROWS / BM), 256>>>(h, fc1_w, fc1_b, nullptr,
                                                     ff, M_ROWS, DFF, DMODEL);

    // 7) out = ff @ fc2_w^T + fc2_b + x1   (in-place residual: read-then-write same element)
    gemm_nt<2><<<dim3(DMODEL / BN, M_ROWS / BM), 256>>>(ff, fc2_w, fc2_b, out,
                                                        out, M_ROWS, DMODEL, DFF);
}

// round 3
// speedup vs baseline: 2.1635x; 2.1635x over previous
#include <cuda_runtime.h>
#include <cuda_bf16.h>
#include <math.h>
#include <cstdint>

// ---------------------------------------------------------------------------
// Problem constants: B=2, S=2048, D=1024, H=16, hd=64, FF=4096
// ---------------------------------------------------------------------------
#define M_ROWS 4096          // B*S
#define DMODEL 1024
#define D3     3072
#define DFF    4096
#define NHEADS 16
#define HDIM   64
#define SEQ    2048
#define LN_EPS 1e-5f

// ---------------------------------------------------------------------------
// Scratch (device globals — no runtime allocation allowed)
// ---------------------------------------------------------------------------
__device__ float g_h   [(size_t)M_ROWS * DMODEL];   // LN output (tf32-rounded)
__device__ float g_qkv [(size_t)M_ROWS * D3];       // qkv projection (fp32)
__device__ float g_attn[(size_t)M_ROWS * DMODEL];   // attention output (tf32-rounded)
__device__ float g_ff  [(size_t)M_ROWS * DFF];      // gelu(fc1) output (tf32-rounded)
__device__ float g_wc  [12582912];                  // tf32-rounded weights:
// layout: qkv_w @ 0 (3M), out_w @ 3145728 (1M), fc1_w @ 4194304 (4M), fc2_w @ 8388608 (4M)

// ---------------------------------------------------------------------------
// Helpers
// ---------------------------------------------------------------------------
__device__ __forceinline__ float to_tf32(float x) {
    float r;
    asm("cvt.rna.tf32.f32 %0, %1;" : "=f"(r) : "f"(x));
    return r;
}

__device__ __forceinline__ void mma16n8k8(float* d,
                                          uint32_t a0, uint32_t a1, uint32_t a2, uint32_t a3,
                                          uint32_t b0, uint32_t b1) {
    asm volatile("mma.sync.aligned.m16n8k8.row.col.f32.tf32.tf32.f32 "
                 "{%0,%1,%2,%3}, {%4,%5,%6,%7}, {%8,%9}, {%0,%1,%2,%3};"
                 : "+f"(d[0]), "+f"(d[1]), "+f"(d[2]), "+f"(d[3])
                 : "r"(a0), "r"(a1), "r"(a2), "r"(a3), "r"(b0), "r"(b1));
}

__device__ __forceinline__ void cp_async16(uint32_t saddr, const void* gptr) {
    asm volatile("cp.async.cg.shared.global [%0], [%1], 16;" :: "r"(saddr), "l"(gptr));
}
__device__ __forceinline__ void cp_commit() {
    asm volatile("cp.async.commit_group;" ::: "memory");
}
template<int N>
__device__ __forceinline__ void cp_wait() {
    asm volatile("cp.async.wait_group %0;" :: "n"(N) : "memory");
}

__device__ __forceinline__ uint32_t smem_u32(const void* p) {
    uint32_t a;
    asm("{ .reg .u64 t; cvta.to.shared.u64 t, %1; cvt.u32.u64 %0, t; }"
        : "=r"(a) : "l"(p));
    return a;
}

__device__ __forceinline__ float gelu_exact(float v) {
    return 0.5f * v * (1.0f + erff(v * 0.70710678118654752f));
}

// ---------------------------------------------------------------------------
// Weight tf32-rounding kernel (elementwise, float4)
// ---------------------------------------------------------------------------
__global__ void cvt_tf32_kernel(const float* __restrict__ in,
                                float* __restrict__ out, int n4)
{
    int i = blockIdx.x * 256 + threadIdx.x;
    if (i < n4) {
        float4 v = ((const float4*)in)[i];
        v.x = to_tf32(v.x); v.y = to_tf32(v.y);
        v.z = to_tf32(v.z); v.w = to_tf32(v.w);
        ((float4*)out)[i] = v;
    }
}

// ---------------------------------------------------------------------------
// TF32 mma.sync NT GEMM: C[M,N] = A[M,K] * W[N,K]^T + bias (+ epilogue)
// Tile 128x128, BK=32, 256 threads (8 warps, 2x4), warp tile 64x32.
// A, W must be tf32-pre-rounded fp32. Double-buffered cp.async SMEM.
// EPI: 0 = bias, 1 = bias + exact GELU (+tf32 round), 2 = bias + residual add
// SMEM (floats): As[2][128*36] @ 0, Bs[2][128*36] @ 9216  (73728 bytes)
// ---------------------------------------------------------------------------
#define GEMM_SMEM_BYTES 73728
#define LDS_STRIDE 36      // 32 + 4 pad floats per row

template<int EPI>
__global__ __launch_bounds__(256, 2)
void gemm_mma(const float* __restrict__ A, const float* __restrict__ W,
              const float* __restrict__ bias, const float* __restrict__ res,
              float* __restrict__ C, int M, int N, int K)
{
    extern __shared__ float smem[];
    const uint32_t sbase = smem_u32(smem);

    const int tid  = threadIdx.x;
    const int w    = tid >> 5;
    const int lane = tid & 31;
    const int g    = lane >> 2;     // 0..7
    const int tig  = lane & 3;      // 0..3

    const int bm = blockIdx.y * 128;
    const int bn = blockIdx.x * 128;
    const int rbase = (w & 1) * 64;       // warp M offset
    const int cbase = (w >> 1) * 32;      // warp N offset

    // loader mapping: 256 threads cover 128 rows x 8 chunks(16B), 4 rows-passes
    const int lr = tid >> 3;              // 0..31
    const int lc = tid & 7;               // 0..7 (16B chunk in 128B row)

    const int nst = K >> 5;

    float acc[4][4][4];
    #pragma unroll
    for (int i = 0; i < 4; i++)
        #pragma unroll
        for (int j = 0; j < 4; j++)
            #pragma unroll
            for (int r = 0; r < 4; r++) acc[i][j][r] = 0.f;

    // ---- stage loader ----
    auto load_stage = [&](int s) {
        const int buf = s & 1;
        const int k0 = s << 5;
        const uint32_t dA = sbase + (uint32_t)(buf * 4608 + lr * LDS_STRIDE + lc * 4) * 4;
        const uint32_t dB = sbase + (uint32_t)(9216 + buf * 4608 + lr * LDS_STRIDE + lc * 4) * 4;
        const float* Ag = A + (size_t)(bm + lr) * K + k0 + lc * 4;
        const float* Wg = W + (size_t)(bn + lr) * K + k0 + lc * 4;
        #pragma unroll
        for (int it = 0; it < 4; it++) {
            cp_async16(dA + it * 32 * LDS_STRIDE * 4, Ag + (size_t)(it * 32) * K);
            cp_async16(dB + it * 32 * LDS_STRIDE * 4, Wg + (size_t)(it * 32) * K);
        }
    };

    load_stage(0);
    cp_commit();

    for (int s = 0; s < nst; s++) {
        cp_wait<0>();
        __syncthreads();

        if (s + 1 < nst) {
            load_stage(s + 1);
            cp_commit();
        }

        const uint32_t* Asu = (const uint32_t*)(smem + (s & 1) * 4608);
        const uint32_t* Bsu = (const uint32_t*)(smem + 9216 + (s & 1) * 4608);

        #pragma unroll
        for (int ks = 0; ks < 4; ks++) {
            const int kk = ks * 8;
            uint32_t a[4][4];
            uint32_t b[4][2];
            #pragma unroll
            for (int i = 0; i < 4; i++) {
                const int r0 = rbase + i * 16 + g;
                a[i][0] = Asu[r0 * LDS_STRIDE + kk + tig];
                a[i][1] = Asu[(r0 + 8) * LDS_STRIDE + kk + tig];
                a[i][2] = Asu[r0 * LDS_STRIDE + kk + tig + 4];
                a[i][3] = Asu[(r0 + 8) * LDS_STRIDE + kk + tig + 4];
            }
            #pragma unroll
            for (int j = 0; j < 4; j++) {
                const int c0 = cbase + j * 8 + g;
                b[j][0] = Bsu[c0 * LDS_STRIDE + kk + tig];
                b[j][1] = Bsu[c0 * LDS_STRIDE + kk + tig + 4];
            }
            #pragma unroll
            for (int i = 0; i < 4; i++)
                #pragma unroll
                for (int j = 0; j < 4; j++)
                    mma16n8k8(acc[i][j], a[i][0], a[i][1], a[i][2], a[i][3],
                              b[j][0], b[j][1]);
        }
    }

    // ---- epilogue ----
    #pragma unroll
    for (int i = 0; i < 4; i++) {
        #pragma unroll
        for (int half = 0; half < 2; half++) {
            const size_t row = (size_t)(bm + rbase + i * 16 + g + half * 8);
            float* crow = C + row * N + bn;
            const float* rrow = (EPI == 2) ? (res + row * N + bn) : nullptr;
            #pragma unroll
            for (int j = 0; j < 4; j++) {
                const int col = cbase + j * 8 + 2 * tig;
                float2 b2 = *(const float2*)(bias + bn + col);
                float vx = acc[i][j][half * 2 + 0] + b2.x;
                float vy = acc[i][j][half * 2 + 1] + b2.y;
                if (EPI == 1) {
                    vx = to_tf32(gelu_exact(vx));
                    vy = to_tf32(gelu_exact(vy));
                }
                if (EPI == 2) {
                    float2 r2 = *(const float2*)(rrow + col);
                    vx += r2.x; vy += r2.y;
                }
                float2 o; o.x = vx; o.y = vy;
                *(float2*)(crow + col) = o;
            }
        }
    }
}

// ---------------------------------------------------------------------------
// LayerNorm: one block per row, 256 threads * 4 floats; output tf32-rounded
// ---------------------------------------------------------------------------
__global__ void ln_kernel(const float* __restrict__ x,
                          const float* __restrict__ gamma,
                          const float* __restrict__ beta,
                          float* __restrict__ y)
{
    const int row = blockIdx.x;
    const int t = threadIdx.x;
    const float4* xr = (const float4*)(x + (size_t)row * DMODEL);
    float4 xv = xr[t];

    __shared__ float red[8];
    __shared__ float stats[2];

    float s = xv.x + xv.y + xv.z + xv.w;
    #pragma unroll
    for (int o = 16; o > 0; o >>= 1) s += __shfl_xor_sync(0xffffffffu, s, o);
    if ((t & 31) == 0) red[t >> 5] = s;
    __syncthreads();
    if (t == 0) {
        float tot = 0.f;
        #pragma unroll
        for (int i = 0; i < 8; i++) tot += red[i];
        stats[0] = tot * (1.0f / DMODEL);
    }
    __syncthreads();
    const float mean = stats[0];

    float dx = xv.x - mean, dy = xv.y - mean, dz = xv.z - mean, dw = xv.w - mean;
    float s2 = dx*dx + dy*dy + dz*dz + dw*dw;
    #pragma unroll
    for (int o = 16; o > 0; o >>= 1) s2 += __shfl_xor_sync(0xffffffffu, s2, o);
    if ((t & 31) == 0) red[t >> 5] = s2;
    __syncthreads();
    if (t == 0) {
        float tot = 0.f;
        #pragma unroll
        for (int i = 0; i < 8; i++) tot += red[i];
        stats[1] = rsqrtf(tot * (1.0f / DMODEL) + LN_EPS);
    }
    __syncthreads();
    const float rstd = stats[1];

    float4 g4 = ((const float4*)gamma)[t];
    float4 b4 = ((const float4*)beta)[t];
    float4 o;
    o.x = to_tf32(dx * rstd * g4.x + b4.x);
    o.y = to_tf32(dy * rstd * g4.y + b4.y);
    o.z = to_tf32(dz * rstd * g4.z + b4.z);
    o.w = to_tf32(dw * rstd * g4.w + b4.w);
    ((float4*)(y + (size_t)row * DMODEL))[t] = o;
}

// ---------------------------------------------------------------------------
// Flash attention (causal), fp32; output tf32-rounded for the out-proj GEMM.
// ---------------------------------------------------------------------------
#define ATT_SMEM_FLOATS (64*64*3 + 64*65 + 128)
#define ATT_SMEM_BYTES  (ATT_SMEM_FLOATS * 4)

__global__ __launch_bounds__(256)
void attn_kernel(const float* __restrict__ qkv, float* __restrict__ out)
{
    extern __shared__ float sm[];
    float* Qt = sm;                 // [d][q]   64x64 (d-major), pre-scaled
    float* Ks = sm + 4096;          // [k][d]   64x64
    float* Vs = sm + 8192;          // [k][d]   64x64
    float* St = sm + 12288;         // [k][q]   64x65 (padded)
    float* scale_s = sm + 12288 + 64 * 65;
    float* l_s     = scale_s + 64;

    const int qt = blockIdx.x;
    const int h  = blockIdx.y;
    const int b  = blockIdx.z;
    const int tid = threadIdx.x;
    const int tx = tid & 15, ty = tid >> 4;

    const size_t rs = D3;
    const float* qbase = qkv + (size_t)b * SEQ * rs + h * HDIM;
    const float* kbase = qbase + DMODEL;
    const float* vbase = qbase + 2 * DMODEL;

    {
        const int r = tid >> 4, c4 = tid & 15;
        #pragma unroll
        for (int p = 0; p < 4; p++) {
            const int row = r + p * 16;
            float4 q4 = *(const float4*)(qbase + (size_t)(qt * 64 + row) * rs + c4 * 4);
            const float s = 0.125f;
            Qt[(c4*4 + 0) * 64 + row] = q4.x * s;
            Qt[(c4*4 + 1) * 64 + row] = q4.y * s;
            Qt[(c4*4 + 2) * 64 + row] = q4.z * s;
            Qt[(c4*4 + 3) * 64 + row] = q4.w * s;
        }
    }

    float m_i = -1e30f, l_i = 0.f;
    float acc[4][4];
    #pragma unroll
    for (int i = 0; i < 4; i++)
        #pragma unroll
        for (int j = 0; j < 4; j++) acc[i][j] = 0.f;

    __syncthreads();

    for (int kt = 0; kt <= qt; kt++) {
        {
            const int r = tid >> 4, c4 = tid & 15;
            #pragma unroll
            for (int p = 0; p < 4; p++) {
                const int row = r + p * 16;
                const size_t g = (size_t)(kt * 64 + row) * rs + c4 * 4;
                *(float4*)(Ks + row * 64 + c4 * 4) = *(const float4*)(kbase + g);
                *(float4*)(Vs + row * 64 + c4 * 4) = *(const float4*)(vbase + g);
            }
        }
        __syncthreads();

        float sacc[4][4];
        #pragma unroll
        for (int i = 0; i < 4; i++)
            #pragma unroll
            for (int j = 0; j < 4; j++) sacc[i][j] = 0.f;

        #pragma unroll 16
        for (int d = 0; d < 64; d++) {
            float a0 = Ks[(ty*4 + 0) * 64 + d];
            float a1 = Ks[(ty*4 + 1) * 64 + d];
            float a2 = Ks[(ty*4 + 2) * 64 + d];
            float a3 = Ks[(ty*4 + 3) * 64 + d];
            float4 qv = *(const float4*)&Qt[d * 64 + tx * 4];
            sacc[0][0] = fmaf(a0, qv.x, sacc[0][0]); sacc[0][1] = fmaf(a0, qv.y, sacc[0][1]);
            sacc[0][2] = fmaf(a0, qv.z, sacc[0][2]); sacc[0][3] = fmaf(a0, qv.w, sacc[0][3]);
            sacc[1][0] = fmaf(a1, qv.x, sacc[1][0]); sacc[1][1] = fmaf(a1, qv.y, sacc[1][1]);
            sacc[1][2] = fmaf(a1, qv.z, sacc[1][2]); sacc[1][3] = fmaf(a1, qv.w, sacc[1][3]);
            sacc[2][0] = fmaf(a2, qv.x, sacc[2][0]); sacc[2][1] = fmaf(a2, qv.y, sacc[2][1]);
            sacc[2][2] = fmaf(a2, qv.z, sacc[2][2]); sacc[2][3] = fmaf(a2, qv.w, sacc[2][3]);
            sacc[3][0] = fmaf(a3, qv.x, sacc[3][0]); sacc[3][1] = fmaf(a3, qv.y, sacc[3][1]);
            sacc[3][2] = fmaf(a3, qv.z, sacc[3][2]); sacc[3][3] = fmaf(a3, qv.w, sacc[3][3]);
        }

        const bool diag = (kt == qt);
        #pragma unroll
        for (int i = 0; i < 4; i++) {
            const int krow = ty * 4 + i;
            #pragma unroll
            for (int j = 0; j < 4; j++) {
                const int qcol = tx * 4 + j;
                float v = sacc[i][j];
                if (diag && krow > qcol) v = -1e30f;
                St[krow * 65 + qcol] = v;
            }
        }
        __syncthreads();

        if (tid < 64) {
            float mx = m_i;
            #pragma unroll 8
            for (int k = 0; k < 64; k++) mx = fmaxf(mx, St[k * 65 + tid]);
            const float fac = __expf(m_i - mx);
            float lsum = 0.f;
            #pragma unroll 8
            for (int k = 0; k < 64; k++) {
                float p = __expf(St[k * 65 + tid] - mx);
                St[k * 65 + tid] = p;
                lsum += p;
            }
            m_i = mx;
            l_i = l_i * fac + lsum;
            scale_s[tid] = fac;
        }
        __syncthreads();

        float sc[4];
        #pragma unroll
        for (int i = 0; i < 4; i++) sc[i] = scale_s[ty * 4 + i];
        #pragma unroll
        for (int i = 0; i < 4; i++)
            #pragma unroll
            for (int j = 0; j < 4; j++) acc[i][j] *= sc[i];

        #pragma unroll 8
        for (int kk = 0; kk < 64; kk++) {
            float p0 = St[kk * 65 + ty*4 + 0];
            float p1 = St[kk * 65 + ty*4 + 1];
            float p2 = St[kk * 65 + ty*4 + 2];
            float p3 = St[kk * 65 + ty*4 + 3];
            float4 vv = *(const float4*)&Vs[kk * 64 + tx * 4];
            acc[0][0] = fmaf(p0, vv.x, acc[0][0]); acc[0][1] = fmaf(p0, vv.y, acc[0][1]);
            acc[0][2] = fmaf(p0, vv.z, acc[0][2]); acc[0][3] = fmaf(p0, vv.w, acc[0][3]);
            acc[1][0] = fmaf(p1, vv.x, acc[1][0]); acc[1][1] = fmaf(p1, vv.y, acc[1][1]);
            acc[1][2] = fmaf(p1, vv.z, acc[1][2]); acc[1][3] = fmaf(p1, vv.w, acc[1][3]);
            acc[2][0] = fmaf(p2, vv.x, acc[2][0]); acc[2][1] = fmaf(p2, vv.y, acc[2][1]);
            acc[2][2] = fmaf(p2, vv.z, acc[2][2]); acc[2][3] = fmaf(p2, vv.w, acc[2][3]);
            acc[3][0] = fmaf(p3, vv.x, acc[3][0]); acc[3][1] = fmaf(p3, vv.y, acc[3][1]);
            acc[3][2] = fmaf(p3, vv.z, acc[3][2]); acc[3][3] = fmaf(p3, vv.w, acc[3][3]);
        }
        __syncthreads();
    }

    if (tid < 64) l_s[tid] = l_i;
    __syncthreads();

    #pragma unroll
    for (int i = 0; i < 4; i++) {
        const int q = ty * 4 + i;
        const float inv = 1.0f / l_s[q];
        float4 o;
        o.x = to_tf32(acc[i][0] * inv);
        o.y = to_tf32(acc[i][1] * inv);
        o.z = to_tf32(acc[i][2] * inv);
        o.w = to_tf32(acc[i][3] * inv);
        *(float4*)(out + (size_t)(b * SEQ + qt * 64 + q) * DMODEL + h * HDIM + tx * 4) = o;
    }
}

// ---------------------------------------------------------------------------
// Launch
// ---------------------------------------------------------------------------
extern "C" void kernel_launch(void* const* d_in, const int* in_sizes, int n_in,
                              void* d_out, int out_size)
{
    const float* x     = (const float*)d_in[0];
    const float* ln1_g = (const float*)d_in[1];
    const float* ln1_b = (const float*)d_in[2];
    const float* qkv_w = (const float*)d_in[3];
    const float* qkv_b = (const float*)d_in[4];
    const float* out_w = (const float*)d_in[5];
    const float* out_b = (const float*)d_in[6];
    const float* ln2_g = (const float*)d_in[7];
    const float* ln2_b = (const float*)d_in[8];
    const float* fc1_w = (const float*)d_in[9];
    const float* fc1_b = (const float*)d_in[10];
    const float* fc2_w = (const float*)d_in[11];
    const float* fc2_b = (const float*)d_in[12];
    float* out = (float*)d_out;

    float *h, *qkv, *attn, *ff, *wc;
    cudaGetSymbolAddress((void**)&h,    g_h);
    cudaGetSymbolAddress((void**)&qkv,  g_qkv);
    cudaGetSymbolAddress((void**)&attn, g_attn);
    cudaGetSymbolAddress((void**)&ff,   g_ff);
    cudaGetSymbolAddress((void**)&wc,   g_wc);

    float* wq = wc;                 // 3M
    float* wo = wc + 3145728;       // 1M
    float* w1 = wc + 4194304;       // 4M
    float* w2 = wc + 8388608;       // 4M

    cudaFuncSetAttribute(attn_kernel,
                         cudaFuncAttributeMaxDynamicSharedMemorySize, ATT_SMEM_BYTES);
    cudaFuncSetAttribute(gemm_mma<0>,
                         cudaFuncAttributeMaxDynamicSharedMemorySize, GEMM_SMEM_BYTES);
    cudaFuncSetAttribute(gemm_mma<1>,
                         cudaFuncAttributeMaxDynamicSharedMemorySize, GEMM_SMEM_BYTES);
    cudaFuncSetAttribute(gemm_mma<2>,
                         cudaFuncAttributeMaxDynamicSharedMemorySize, GEMM_SMEM_BYTES);

    // 0) tf32-round the weights (once per replay; ~20us)
    cvt_tf32_kernel<<<(D3*DMODEL/4 + 255)/256, 256>>>(qkv_w, wq, D3*DMODEL/4);
    cvt_tf32_kernel<<<(DMODEL*DMODEL/4 + 255)/256, 256>>>(out_w, wo, DMODEL*DMODEL/4);
    cvt_tf32_kernel<<<(DFF*DMODEL/4 + 255)/256, 256>>>(fc1_w, w1, DFF*DMODEL/4);
    cvt_tf32_kernel<<<(DMODEL*DFF/4 + 255)/256, 256>>>(fc2_w, w2, DMODEL*DFF/4);

    // 1) h = tf32(LN1(x))
    ln_kernel<<<M_ROWS, 256>>>(x, ln1_g, ln1_b, h);

    // 2) qkv = h @ wq^T + qkv_b
    gemm_mma<0><<<dim3(D3 / 128, M_ROWS / 128), 256, GEMM_SMEM_BYTES>>>(
        h, wq, qkv_b, nullptr, qkv, M_ROWS, D3, DMODEL);

    // 3) attn = tf32(causal_flash_attention(qkv))
    attn_kernel<<<dim3(SEQ / 64, NHEADS, 2), 256, ATT_SMEM_BYTES>>>(qkv, attn);

    // 4) x1 = attn @ wo^T + out_b + x
    gemm_mma<2><<<dim3(DMODEL / 128, M_ROWS / 128), 256, GEMM_SMEM_BYTES>>>(
        attn, wo, out_b, x, out, M_ROWS, DMODEL, DMODEL);

    // 5) h = tf32(LN2(x1))
    ln_kernel<<<M_ROWS, 256>>>(out, ln2_g, ln2_b, h);

    // 6) ff = tf32(gelu(h @ w1^T + fc1_b))
    gemm_mma<1><<<dim3(DFF / 128, M_ROWS / 128), 256, GEMM_SMEM_BYTES>>>(
        h, w1, fc1_b, nullptr, ff, M_ROWS, DFF, DMODEL);

    // 7) out = ff @ w2^T + fc2_b + x1
    gemm_mma<2><<<dim3(DMODEL / 128, M_ROWS / 128), 256, GEMM_SMEM_BYTES>>>(
        ff, w2, fc2_b, out, out, M_ROWS, DMODEL, DFF);
}

// round 4
// speedup vs baseline: 2.8986x; 1.3398x over previous
#include <cuda_runtime.h>
#include <cuda_bf16.h>
#include <math.h>
#include <cstdint>

// ---------------------------------------------------------------------------
// Problem constants: B=2, S=2048, D=1024, H=16, hd=64, FF=4096
// ---------------------------------------------------------------------------
#define M_ROWS 4096          // B*S
#define DMODEL 1024
#define D3     3072
#define DFF    4096
#define NHEADS 16
#define HDIM   64
#define SEQ    2048
#define LN_EPS 1e-5f

// ---------------------------------------------------------------------------
// Scratch (device globals — no runtime allocation allowed)
// ---------------------------------------------------------------------------
__device__ float g_h   [(size_t)M_ROWS * DMODEL];   // LN output (tf32-rounded)
__device__ float g_qkv [(size_t)M_ROWS * D3];       // qkv projection (fp32)
__device__ float g_attn[(size_t)M_ROWS * DMODEL];   // attention output (tf32-rounded)
__device__ float g_ff  [(size_t)M_ROWS * DFF];      // gelu(fc1) output (tf32-rounded)
__device__ float g_wc  [12582912];                  // tf32-rounded weights

// ---------------------------------------------------------------------------
// Helpers
// ---------------------------------------------------------------------------
__device__ __forceinline__ float to_tf32(float x) {
    float r;
    asm("cvt.rna.tf32.f32 %0, %1;" : "=f"(r) : "f"(x));
    return r;
}

__device__ __forceinline__ void mma16n8k8(float* d,
                                          uint32_t a0, uint32_t a1, uint32_t a2, uint32_t a3,
                                          uint32_t b0, uint32_t b1) {
    asm volatile("mma.sync.aligned.m16n8k8.row.col.f32.tf32.tf32.f32 "
                 "{%0,%1,%2,%3}, {%4,%5,%6,%7}, {%8,%9}, {%0,%1,%2,%3};"
                 : "+f"(d[0]), "+f"(d[1]), "+f"(d[2]), "+f"(d[3])
                 : "r"(a0), "r"(a1), "r"(a2), "r"(a3), "r"(b0), "r"(b1));
}

__device__ __forceinline__ void cp_async16(uint32_t saddr, const void* gptr) {
    asm volatile("cp.async.cg.shared.global [%0], [%1], 16;" :: "r"(saddr), "l"(gptr));
}
__device__ __forceinline__ void cp_commit() {
    asm volatile("cp.async.commit_group;" ::: "memory");
}
template<int N>
__device__ __forceinline__ void cp_wait() {
    asm volatile("cp.async.wait_group %0;" :: "n"(N) : "memory");
}

__device__ __forceinline__ uint32_t smem_u32(const void* p) {
    uint32_t a;
    asm("{ .reg .u64 t; cvta.to.shared.u64 t, %1; cvt.u32.u64 %0, t; }"
        : "=r"(a) : "l"(p));
    return a;
}

__device__ __forceinline__ float gelu_exact(float v) {
    return 0.5f * v * (1.0f + erff(v * 0.70710678118654752f));
}

// ---------------------------------------------------------------------------
// Weight tf32-rounding kernel (elementwise, float4)
// ---------------------------------------------------------------------------
__global__ void cvt_tf32_kernel(const float* __restrict__ in,
                                float* __restrict__ out, int n4)
{
    int i = blockIdx.x * 256 + threadIdx.x;
    if (i < n4) {
        float4 v = ((const float4*)in)[i];
        v.x = to_tf32(v.x); v.y = to_tf32(v.y);
        v.z = to_tf32(v.z); v.w = to_tf32(v.w);
        ((float4*)out)[i] = v;
    }
}

// ---------------------------------------------------------------------------
// TF32 mma.sync NT GEMM: C[M,N] = A[M,K] * W[N,K]^T + bias (+ epilogue)
// Tile 128x128, BK=32, 256 threads (8 warps, 2x4), warp tile 64x32.
// (unchanged from round 3 — known good, ~108 TF/s)
// ---------------------------------------------------------------------------
#define GEMM_SMEM_BYTES 73728
#define LDS_STRIDE 36      // 32 + 4 pad floats per row

template<int EPI>
__global__ __launch_bounds__(256, 2)
void gemm_mma(const float* __restrict__ A, const float* __restrict__ W,
              const float* __restrict__ bias, const float* __restrict__ res,
              float* __restrict__ C, int M, int N, int K)
{
    extern __shared__ float smem[];
    const uint32_t sbase = smem_u32(smem);

    const int tid  = threadIdx.x;
    const int w    = tid >> 5;
    const int lane = tid & 31;
    const int g    = lane >> 2;     // 0..7
    const int tig  = lane & 3;      // 0..3

    const int bm = blockIdx.y * 128;
    const int bn = blockIdx.x * 128;
    const int rbase = (w & 1) * 64;       // warp M offset
    const int cbase = (w >> 1) * 32;      // warp N offset

    const int lr = tid >> 3;              // 0..31
    const int lc = tid & 7;               // 0..7 (16B chunk in 128B row)

    const int nst = K >> 5;

    float acc[4][4][4];
    #pragma unroll
    for (int i = 0; i < 4; i++)
        #pragma unroll
        for (int j = 0; j < 4; j++)
            #pragma unroll
            for (int r = 0; r < 4; r++) acc[i][j][r] = 0.f;

    auto load_stage = [&](int s) {
        const int buf = s & 1;
        const int k0 = s << 5;
        const uint32_t dA = sbase + (uint32_t)(buf * 4608 + lr * LDS_STRIDE + lc * 4) * 4;
        const uint32_t dB = sbase + (uint32_t)(9216 + buf * 4608 + lr * LDS_STRIDE + lc * 4) * 4;
        const float* Ag = A + (size_t)(bm + lr) * K + k0 + lc * 4;
        const float* Wg = W + (size_t)(bn + lr) * K + k0 + lc * 4;
        #pragma unroll
        for (int it = 0; it < 4; it++) {
            cp_async16(dA + it * 32 * LDS_STRIDE * 4, Ag + (size_t)(it * 32) * K);
            cp_async16(dB + it * 32 * LDS_STRIDE * 4, Wg + (size_t)(it * 32) * K);
        }
    };

    load_stage(0);
    cp_commit();

    for (int s = 0; s < nst; s++) {
        cp_wait<0>();
        __syncthreads();

        if (s + 1 < nst) {
            load_stage(s + 1);
            cp_commit();
        }

        const uint32_t* Asu = (const uint32_t*)(smem + (s & 1) * 4608);
        const uint32_t* Bsu = (const uint32_t*)(smem + 9216 + (s & 1) * 4608);

        #pragma unroll
        for (int ks = 0; ks < 4; ks++) {
            const int kk = ks * 8;
            uint32_t a[4][4];
            uint32_t b[4][2];
            #pragma unroll
            for (int i = 0; i < 4; i++) {
                const int r0 = rbase + i * 16 + g;
                a[i][0] = Asu[r0 * LDS_STRIDE + kk + tig];
                a[i][1] = Asu[(r0 + 8) * LDS_STRIDE + kk + tig];
                a[i][2] = Asu[r0 * LDS_STRIDE + kk + tig + 4];
                a[i][3] = Asu[(r0 + 8) * LDS_STRIDE + kk + tig + 4];
            }
            #pragma unroll
            for (int j = 0; j < 4; j++) {
                const int c0 = cbase + j * 8 + g;
                b[j][0] = Bsu[c0 * LDS_STRIDE + kk + tig];
                b[j][1] = Bsu[c0 * LDS_STRIDE + kk + tig + 4];
            }
            #pragma unroll
            for (int i = 0; i < 4; i++)
                #pragma unroll
                for (int j = 0; j < 4; j++)
                    mma16n8k8(acc[i][j], a[i][0], a[i][1], a[i][2], a[i][3],
                              b[j][0], b[j][1]);
        }
    }

    #pragma unroll
    for (int i = 0; i < 4; i++) {
        #pragma unroll
        for (int half = 0; half < 2; half++) {
            const size_t row = (size_t)(bm + rbase + i * 16 + g + half * 8);
            float* crow = C + row * N + bn;
            const float* rrow = (EPI == 2) ? (res + row * N + bn) : nullptr;
            #pragma unroll
            for (int j = 0; j < 4; j++) {
                const int col = cbase + j * 8 + 2 * tig;
                float2 b2 = *(const float2*)(bias + bn + col);
                float vx = acc[i][j][half * 2 + 0] + b2.x;
                float vy = acc[i][j][half * 2 + 1] + b2.y;
                if (EPI == 1) {
                    vx = to_tf32(gelu_exact(vx));
                    vy = to_tf32(gelu_exact(vy));
                }
                if (EPI == 2) {
                    float2 r2 = *(const float2*)(rrow + col);
                    vx += r2.x; vy += r2.y;
                }
                float2 o; o.x = vx; o.y = vy;
                *(float2*)(crow + col) = o;
            }
        }
    }
}

// ---------------------------------------------------------------------------
// LayerNorm: one block per row, 256 threads * 4 floats; output tf32-rounded
// ---------------------------------------------------------------------------
__global__ void ln_kernel(const float* __restrict__ x,
                          const float* __restrict__ gamma,
                          const float* __restrict__ beta,
                          float* __restrict__ y)
{
    const int row = blockIdx.x;
    const int t = threadIdx.x;
    const float4* xr = (const float4*)(x + (size_t)row * DMODEL);
    float4 xv = xr[t];

    __shared__ float red[8];
    __shared__ float stats[2];

    float s = xv.x + xv.y + xv.z + xv.w;
    #pragma unroll
    for (int o = 16; o > 0; o >>= 1) s += __shfl_xor_sync(0xffffffffu, s, o);
    if ((t & 31) == 0) red[t >> 5] = s;
    __syncthreads();
    if (t == 0) {
        float tot = 0.f;
        #pragma unroll
        for (int i = 0; i < 8; i++) tot += red[i];
        stats[0] = tot * (1.0f / DMODEL);
    }
    __syncthreads();
    const float mean = stats[0];

    float dx = xv.x - mean, dy = xv.y - mean, dz = xv.z - mean, dw = xv.w - mean;
    float s2 = dx*dx + dy*dy + dz*dz + dw*dw;
    #pragma unroll
    for (int o = 16; o > 0; o >>= 1) s2 += __shfl_xor_sync(0xffffffffu, s2, o);
    if ((t & 31) == 0) red[t >> 5] = s2;
    __syncthreads();
    if (t == 0) {
        float tot = 0.f;
        #pragma unroll
        for (int i = 0; i < 8; i++) tot += red[i];
        stats[1] = rsqrtf(tot * (1.0f / DMODEL) + LN_EPS);
    }
    __syncthreads();
    const float rstd = stats[1];

    float4 g4 = ((const float4*)gamma)[t];
    float4 b4 = ((const float4*)beta)[t];
    float4 o;
    o.x = to_tf32(dx * rstd * g4.x + b4.x);
    o.y = to_tf32(dy * rstd * g4.y + b4.y);
    o.z = to_tf32(dz * rstd * g4.z + b4.z);
    o.w = to_tf32(dw * rstd * g4.w + b4.w);
    ((float4*)(y + (size_t)row * DMODEL))[t] = o;
}

// ---------------------------------------------------------------------------
// Flash attention (causal) on tensor cores (mma.sync tf32).
// One block per (q-tile 64, head, batch). 256 threads = 8 warps in 4(q)x2(k/d).
// Q/K/V staged in SMEM stride-68 rows; S stored transposed St[k][q] stride 68.
// All fragment LDS / St stores conflict-free by construction.
// ---------------------------------------------------------------------------
#define ASP 68
#define ATT_SMEM_FLOATS (4 * 64 * ASP + 128)
#define ATT_SMEM_BYTES  (ATT_SMEM_FLOATS * 4)

__global__ __launch_bounds__(256)
void attn_mma_kernel(const float* __restrict__ qkv, float* __restrict__ out)
{
    extern __shared__ float sm[];
    float* Qs = sm;                    // [q][d] 64x68, tf32, pre-scaled
    float* Ks = sm + 64 * ASP;         // [k][d] 64x68, tf32
    float* Vs = sm + 2 * 64 * ASP;     // [k][d] 64x68, tf32
    float* St = sm + 3 * 64 * ASP;     // [k][q] 64x68 (scores, then P in tf32)
    float* scale_s = sm + 4 * 64 * ASP;        // [64]
    float* l_s     = sm + 4 * 64 * ASP + 64;   // [64]

    const int qt = (int)gridDim.x - 1 - (int)blockIdx.x;  // big tiles first
    const int h  = blockIdx.y;
    const int b  = blockIdx.z;
    const int tid = threadIdx.x;
    const int w = tid >> 5, lane = tid & 31;
    const int g = lane >> 2, tig = lane & 3;
    const int rbase = (w & 3) * 16;      // q offset of warp tile
    const int cbase = (w >> 2) * 32;     // k (or d) offset of warp tile

    const size_t rs = D3;
    const float* qbase = qkv + (size_t)b * SEQ * rs + h * HDIM;
    const float* kbase = qbase + DMODEL;
    const float* vbase = qbase + 2 * DMODEL;

    // ---- load Q tile (scaled by 1/8, tf32-rounded) ----
    #pragma unroll
    for (int p = 0; p < 4; p++) {
        const int idx = p * 256 + tid;
        const int row = idx >> 4;
        const int quad = idx & 15;
        float4 v = *(const float4*)(qbase + (size_t)(qt * 64 + row) * rs + quad * 4);
        v.x = to_tf32(v.x * 0.125f); v.y = to_tf32(v.y * 0.125f);
        v.z = to_tf32(v.z * 0.125f); v.w = to_tf32(v.w * 0.125f);
        *(float4*)(Qs + row * ASP + quad * 4) = v;
    }

    float m_i = -1e30f, l_i = 0.f;       // owned by threads 0..63 (q = tid)
    float acc[4][4];
    #pragma unroll
    for (int j = 0; j < 4; j++)
        #pragma unroll
        for (int r = 0; r < 4; r++) acc[j][r] = 0.f;

    __syncthreads();

    for (int kt = 0; kt <= qt; kt++) {
        // ---- load K,V tiles (tf32-rounded) ----
        #pragma unroll
        for (int p = 0; p < 4; p++) {
            const int idx = p * 256 + tid;
            const int row = idx >> 4;
            const int quad = idx & 15;
            const size_t goff = (size_t)(kt * 64 + row) * rs + quad * 4;
            float4 kv = *(const float4*)(kbase + goff);
            kv.x = to_tf32(kv.x); kv.y = to_tf32(kv.y);
            kv.z = to_tf32(kv.z); kv.w = to_tf32(kv.w);
            *(float4*)(Ks + row * ASP + quad * 4) = kv;
            float4 vv = *(const float4*)(vbase + goff);
            vv.x = to_tf32(vv.x); vv.y = to_tf32(vv.y);
            vv.z = to_tf32(vv.z); vv.w = to_tf32(vv.w);
            *(float4*)(Vs + row * ASP + quad * 4) = vv;
        }
        __syncthreads();

        // ---- S = Q K^T : warp tile 16(q) x 32(k), 8 K-steps over d ----
        float sacc[4][4];
        #pragma unroll
        for (int j = 0; j < 4; j++)
            #pragma unroll
            for (int r = 0; r < 4; r++) sacc[j][r] = 0.f;

        const uint32_t* Qu = (const uint32_t*)Qs;
        const uint32_t* Ku = (const uint32_t*)Ks;
        #pragma unroll
        for (int ks = 0; ks < 8; ks++) {
            const int kk = ks * 8;
            const int r0 = rbase + g;
            uint32_t a0 = Qu[r0 * ASP + kk + tig];
            uint32_t a1 = Qu[(r0 + 8) * ASP + kk + tig];
            uint32_t a2 = Qu[r0 * ASP + kk + tig + 4];
            uint32_t a3 = Qu[(r0 + 8) * ASP + kk + tig + 4];
            #pragma unroll
            for (int j = 0; j < 4; j++) {
                const int c0 = cbase + j * 8 + g;
                uint32_t b0 = Ku[c0 * ASP + kk + tig];
                uint32_t b1 = Ku[c0 * ASP + kk + tig + 4];
                mma16n8k8(sacc[j], a0, a1, a2, a3, b0, b1);
            }
        }

        // ---- store S transposed (with causal mask on diagonal tile) ----
        const bool diag = (kt == qt);
        #pragma unroll
        for (int j = 0; j < 4; j++) {
            const int k0 = cbase + j * 8 + 2 * tig;
            const int q0 = rbase + g;
            float v00 = sacc[j][0], v01 = sacc[j][1];
            float v10 = sacc[j][2], v11 = sacc[j][3];
            if (diag) {
                if (k0     > q0    ) v00 = -1e30f;
                if (k0 + 1 > q0    ) v01 = -1e30f;
                if (k0     > q0 + 8) v10 = -1e30f;
                if (k0 + 1 > q0 + 8) v11 = -1e30f;
            }
            St[k0       * ASP + q0    ] = v00;
            St[(k0 + 1) * ASP + q0    ] = v01;
            St[k0       * ASP + q0 + 8] = v10;
            St[(k0 + 1) * ASP + q0 + 8] = v11;
        }
        __syncthreads();

        // ---- online softmax: thread t (<64) owns q column t ----
        if (tid < 64) {
            float mx = m_i;
            #pragma unroll 8
            for (int k = 0; k < 64; k++) mx = fmaxf(mx, St[k * ASP + tid]);
            const float fac = __expf(m_i - mx);
            float lsum = 0.f;
            #pragma unroll 8
            for (int k = 0; k < 64; k++) {
                float p = __expf(St[k * ASP + tid] - mx);
                St[k * ASP + tid] = to_tf32(p);
                lsum += p;
            }
            m_i = mx;
            l_i = l_i * fac + lsum;
            scale_s[tid] = fac;
        }
        __syncthreads();

        // ---- rescale O accumulators ----
        const float f0 = scale_s[rbase + g];
        const float f1 = scale_s[rbase + g + 8];
        #pragma unroll
        for (int j = 0; j < 4; j++) {
            acc[j][0] *= f0; acc[j][1] *= f0;
            acc[j][2] *= f1; acc[j][3] *= f1;
        }

        // ---- O += P V : warp tile 16(q) x 32(d), 8 K-steps over k ----
        const uint32_t* Pu = (const uint32_t*)St;
        const uint32_t* Vu = (const uint32_t*)Vs;
        #pragma unroll
        for (int ks = 0; ks < 8; ks++) {
            const int kk = ks * 8;
            const int r0 = rbase + g;
            uint32_t a0 = Pu[(kk + tig)     * ASP + r0];
            uint32_t a1 = Pu[(kk + tig)     * ASP + r0 + 8];
            uint32_t a2 = Pu[(kk + tig + 4) * ASP + r0];
            uint32_t a3 = Pu[(kk + tig + 4) * ASP + r0 + 8];
            #pragma unroll
            for (int j = 0; j < 4; j++) {
                const int c0 = cbase + j * 8 + g;
                uint32_t b0 = Vu[(kk + tig)     * ASP + c0];
                uint32_t b1 = Vu[(kk + tig + 4) * ASP + c0];
                mma16n8k8(acc[j], a0, a1, a2, a3, b0, b1);
            }
        }
        __syncthreads();   // protect Ks/Vs/St before next iteration
    }

    if (tid < 64) l_s[tid] = l_i;
    __syncthreads();

    const float inv0 = 1.0f / l_s[rbase + g];
    const float inv1 = 1.0f / l_s[rbase + g + 8];
    const size_t row0 = (size_t)(b * SEQ + qt * 64 + rbase + g);
    #pragma unroll
    for (int j = 0; j < 4; j++) {
        const int col = h * HDIM + cbase + j * 8 + 2 * tig;
        float2 o0, o1;
        o0.x = to_tf32(acc[j][0] * inv0);
        o0.y = to_tf32(acc[j][1] * inv0);
        o1.x = to_tf32(acc[j][2] * inv1);
        o1.y = to_tf32(acc[j][3] * inv1);
        *(float2*)(out + row0 * DMODEL + col) = o0;
        *(float2*)(out + (row0 + 8) * DMODEL + col) = o1;
    }
}

// ---------------------------------------------------------------------------
// Launch
// ---------------------------------------------------------------------------
extern "C" void kernel_launch(void* const* d_in, const int* in_sizes, int n_in,
                              void* d_out, int out_size)
{
    const float* x     = (const float*)d_in[0];
    const float* ln1_g = (const float*)d_in[1];
    const float* ln1_b = (const float*)d_in[2];
    const float* qkv_w = (const float*)d_in[3];
    const float* qkv_b = (const float*)d_in[4];
    const float* out_w = (const float*)d_in[5];
    const float* out_b = (const float*)d_in[6];
    const float* ln2_g = (const float*)d_in[7];
    const float* ln2_b = (const float*)d_in[8];
    const float* fc1_w = (const float*)d_in[9];
    const float* fc1_b = (const float*)d_in[10];
    const float* fc2_w = (const float*)d_in[11];
    const float* fc2_b = (const float*)d_in[12];
    float* out = (float*)d_out;

    float *h, *qkv, *attn, *ff, *wc;
    cudaGetSymbolAddress((void**)&h,    g_h);
    cudaGetSymbolAddress((void**)&qkv,  g_qkv);
    cudaGetSymbolAddress((void**)&attn, g_attn);
    cudaGetSymbolAddress((void**)&ff,   g_ff);
    cudaGetSymbolAddress((void**)&wc,   g_wc);

    float* wq = wc;                 // 3M
    float* wo = wc + 3145728;       // 1M
    float* w1 = wc + 4194304;       // 4M
    float* w2 = wc + 8388608;       // 4M

    cudaFuncSetAttribute(attn_mma_kernel,
                         cudaFuncAttributeMaxDynamicSharedMemorySize, ATT_SMEM_BYTES);
    cudaFuncSetAttribute(gemm_mma<0>,
                         cudaFuncAttributeMaxDynamicSharedMemorySize, GEMM_SMEM_BYTES);
    cudaFuncSetAttribute(gemm_mma<1>,
                         cudaFuncAttributeMaxDynamicSharedMemorySize, GEMM_SMEM_BYTES);
    cudaFuncSetAttribute(gemm_mma<2>,
                         cudaFuncAttributeMaxDynamicSharedMemorySize, GEMM_SMEM_BYTES);

    // 0) tf32-round the weights
    cvt_tf32_kernel<<<(D3*DMODEL/4 + 255)/256, 256>>>(qkv_w, wq, D3*DMODEL/4);
    cvt_tf32_kernel<<<(DMODEL*DMODEL/4 + 255)/256, 256>>>(out_w, wo, DMODEL*DMODEL/4);
    cvt_tf32_kernel<<<(DFF*DMODEL/4 + 255)/256, 256>>>(fc1_w, w1, DFF*DMODEL/4);
    cvt_tf32_kernel<<<(DMODEL*DFF/4 + 255)/256, 256>>>(fc2_w, w2, DMODEL*DFF/4);

    // 1) h = tf32(LN1(x))
    ln_kernel<<<M_ROWS, 256>>>(x, ln1_g, ln1_b, h);

    // 2) qkv = h @ wq^T + qkv_b
    gemm_mma<0><<<dim3(D3 / 128, M_ROWS / 128), 256, GEMM_SMEM_BYTES>>>(
        h, wq, qkv_b, nullptr, qkv, M_ROWS, D3, DMODEL);

    // 3) attn = tf32(causal_flash_attention(qkv))  [tensor cores]
    attn_mma_kernel<<<dim3(SEQ / 64, NHEADS, 2), 256, ATT_SMEM_BYTES>>>(qkv, attn);

    // 4) x1 = attn @ wo^T + out_b + x
    gemm_mma<2><<<dim3(DMODEL / 128, M_ROWS / 128), 256, GEMM_SMEM_BYTES>>>(
        attn, wo, out_b, x, out, M_ROWS, DMODEL, DMODEL);

    // 5) h = tf32(LN2(x1))
    ln_kernel<<<M_ROWS, 256>>>(out, ln2_g, ln2_b, h);

    // 6) ff = tf32(gelu(h @ w1^T + fc1_b))
    gemm_mma<1><<<dim3(DFF / 128, M_ROWS / 128), 256, GEMM_SMEM_BYTES>>>(
        h, w1, fc1_b, nullptr, ff, M_ROWS, DFF, DMODEL);

    // 7) out = ff @ w2^T + fc2_b + x1
    gemm_mma<2><<<dim3(DMODEL / 128, M_ROWS / 128), 256, GEMM_SMEM_BYTES>>>(
        ff, w2, fc2_b, out, out, M_ROWS, DMODEL, DFF);
}